// round 2
// baseline (speedup 1.0000x reference)
#include <cuda_runtime.h>

typedef unsigned long long u64;

// ---------------- problem constants ----------------
#define BB 16
#define TT 12
#define FF 32
#define H1 48
#define W1 48
#define C1 3
#define HO1 47
#define WO1 46
#define H2 47
#define W2 46
#define C2 32
#define HO2 46
#define WO2 44
#define FLAT 194304
#define NCHUNK 256
#define CHUNK 759   // 256*759 = 194304 exactly

// ---------------- device scratch ----------------
__device__ float g_h1[(long)TT * BB * HO1 * WO1 * FF];
__device__ float g_h2[(long)TT * BB * HO2 * WO2 * FF];
__device__ float g_c[2 * BB * HO1 * WO1 * FF];          // both layers, one memset
__device__ float g_hzero[BB * HO1 * WO1 * FF];          // zero-init, never written
__device__ float g_pool[BB * FLAT];
__device__ float g_part[NCHUNK * BB * 10];
__device__ float4 g_Wr1[6 * C1 * 32];
__device__ float4 g_Ur1[6 * 32 * 32];
__device__ float4 g_Wr2[6 * 32 * 32];
__device__ float4 g_Ur2[6 * 32 * 32];

__device__ __forceinline__ float hsig(float x) {
    return fminf(fmaxf(fmaf(0.2f, x, 0.5f), 0.0f), 1.0f);
}

__device__ __forceinline__ u64 pack2(float lo, float hi) {
    u64 r;
    asm("mov.b64 %0, {%1, %2};" : "=l"(r) : "f"(lo), "f"(hi));
    return r;
}
__device__ __forceinline__ void unpack2(u64 v, float& lo, float& hi) {
    asm("mov.b64 {%0, %1}, %2;" : "=f"(lo), "=f"(hi) : "l"(v));
}
// packed dual-FMA: d = a*b + d (two fp32 lanes in one instruction)
__device__ __forceinline__ void ffma2(u64& d, u64 a, u64 b) {
    asm("fma.rn.f32x2 %0, %1, %2, %0;" : "+l"(d) : "l"(a), "l"(b));
}

// Combined weight reorder: [k(6)][cin][128] -> float4 {i,f,c,o} per (k,cin,f)
__global__ void reorder4_kernel(const float* __restrict__ s1, float4* __restrict__ d1, int n1,
                                const float* __restrict__ s2, float4* __restrict__ d2,
                                const float* __restrict__ s3, float4* __restrict__ d3,
                                const float* __restrict__ s4, float4* __restrict__ d4, int n) {
    int idx = blockIdx.x * blockDim.x + threadIdx.x;
    if (idx < n) {
        int f = idx & 31, kc = idx >> 5;
        const float* s;
        float4* d;
        if (idx < n1) { s = s1 + kc * 128; d = d1 + idx; }
        else { s = s2; d = d2; // dummy init
            int j = idx - n1;
            int seg = j / n; // unused
            (void)seg;
        }
        if (idx < n1) {
            *d = make_float4(s[f], s[32 + f], s[64 + f], s[96 + f]);
        }
    }
    // segments 2..4 (each n elements)
    if (idx >= n1 && idx < n1 + 3 * n) {
        int j = idx - n1;
        int seg = j / n;
        int e = j % n;
        int f = e & 31, kc = e >> 5;
        const float* s = (seg == 0 ? s2 : seg == 1 ? s3 : s4) + kc * 128;
        float4* d = (seg == 0 ? d2 : seg == 1 ? d3 : d4) + e;
        *d = make_float4(s[f], s[32 + f], s[64 + f], s[96 + f]);
    }
}

// One fused ConvLSTM timestep, f32x2-packed gate pairs.
// Grid (tilesX, tilesY, B); block 256 = 8 warps (warp=row, lane=filter).
template <int CIN>
__global__ void __launch_bounds__(256, 2) step_kernel(
    const float* __restrict__ xin, int xbstride, int H, int W,
    const float* __restrict__ hprev,
    float* __restrict__ cbuf,
    float* __restrict__ hout,
    const float4* __restrict__ Wr, const float4* __restrict__ Ur,
    const float* __restrict__ bias,
    int Ho, int Wo)
{
    __shared__ u64 xs[9][10][CIN]; // {v,v} duplicated pairs
    __shared__ u64 hs[9][10][32];

    const int tid = threadIdx.x;
    const int f = tid & 31;
    const int wp = tid >> 5;
    const int b = blockIdx.z;
    const int y0 = blockIdx.y * 8;
    const int x0 = blockIdx.x * 8;
    const int hb = Ho * Wo * 32;

    // stage x patch (duplicated)
    for (int i = tid; i < 9 * 10 * CIN; i += 256) {
        int ci = i % CIN; int t2 = i / CIN;
        int cx = t2 % 10; int r = t2 / 10;
        int gy = y0 + r, gx = x0 + cx;
        float v = 0.0f;
        if (gy < H && gx < W)
            v = xin[(long)b * xbstride + (gy * W + gx) * CIN + ci];
        xs[r][cx][ci] = pack2(v, v);
    }
    // stage h patch (SAME pad: top 0/bottom 1, left 1/right 1)
    for (int i = tid; i < 9 * 10 * 32; i += 256) {
        int ci = i & 31; int t2 = i >> 5;
        int cx = t2 % 10; int r = t2 / 10;
        int gy = y0 + r, gx = x0 + cx - 1;
        float v = 0.0f;
        if (gy < Ho && gx >= 0 && gx < Wo)
            v = hprev[(long)b * hb + (gy * Wo + gx) * 32 + ci];
        hs[r][cx][ci] = pack2(v, v);
    }
    __syncthreads();

    u64 aif[8], aco[8];
    {
        u64 bif = pack2(bias[f], bias[32 + f]);
        u64 bco = pack2(bias[64 + f], bias[96 + f]);
#pragma unroll
        for (int p = 0; p < 8; p++) { aif[p] = bif; aco[p] = bco; }
    }

    // input conv (VALID)
#pragma unroll
    for (int k = 0; k < 6; k++) {
        const int dy = k / 3, dx = k % 3;
#pragma unroll 4
        for (int ci = 0; ci < CIN; ci++) {
            float4 w = Wr[(k * CIN + ci) * 32 + f];
            u64 wif = pack2(w.x, w.y);
            u64 wco = pack2(w.z, w.w);
#pragma unroll
            for (int p = 0; p < 8; p++) {
                u64 vv = xs[wp + dy][p + dx][ci];
                ffma2(aif[p], vv, wif);
                ffma2(aco[p], vv, wco);
            }
        }
    }
    // recurrent conv (SAME)
#pragma unroll
    for (int k = 0; k < 6; k++) {
        const int dy = k / 3, dx = k % 3;
#pragma unroll 4
        for (int ci = 0; ci < 32; ci++) {
            float4 w = Ur[(k * 32 + ci) * 32 + f];
            u64 wif = pack2(w.x, w.y);
            u64 wco = pack2(w.z, w.w);
#pragma unroll
            for (int p = 0; p < 8; p++) {
                u64 vv = hs[wp + dy][p + dx][ci];
                ffma2(aif[p], vv, wif);
                ffma2(aco[p], vv, wco);
            }
        }
    }

    const int y = y0 + wp;
    if (y < Ho) {
#pragma unroll
        for (int p = 0; p < 8; p++) {
            int gx = x0 + p;
            if (gx < Wo) {
                long o = (long)b * hb + (y * Wo + gx) * 32 + f;
                float zi, zf, zc, zo;
                unpack2(aif[p], zi, zf);
                unpack2(aco[p], zc, zo);
                float cold = cbuf[o];
                float ig = hsig(zi);
                float fg = hsig(zf);
                float cn = fmaf(fg, cold, ig * fmaxf(zc, 0.0f));
                cbuf[o] = cn;
                hout[o] = hsig(zo) * fmaxf(cn, 0.0f);
            }
        }
    }
}

// MaxPool (1,2,2): h2 [T][B][46][44][32] -> pool [B][T][23][22][32]
__global__ void pool_kernel(const float* __restrict__ h2, float* __restrict__ pout) {
    int idx = blockIdx.x * blockDim.x + threadIdx.x;
    if (idx >= BB * TT * 23 * 22 * 32) return;
    int c = idx & 31; int t2 = idx >> 5;
    int pw = t2 % 22; t2 /= 22;
    int ph = t2 % 23; t2 /= 23;
    int t = t2 % TT; int b = t2 / TT;
    const float* base = h2 + (((long)(t * BB + b) * HO2 + 2 * ph) * WO2 + 2 * pw) * 32 + c;
    float m = fmaxf(fmaxf(base[0], base[32]),
                    fmaxf(base[WO2 * 32], base[WO2 * 32 + 32]));
    pout[idx] = m;
}

__global__ void __launch_bounds__(128) dense_part_kernel(
    const float* __restrict__ pool, const float* __restrict__ Wd1, float* __restrict__ part)
{
    int ch = blockIdx.x, b = blockIdx.y;
    int start = ch * CHUNK;
    float s[10];
#pragma unroll
    for (int j = 0; j < 10; j++) s[j] = 0.0f;
    for (int i = start + threadIdx.x; i < start + CHUNK; i += 128) {
        float v = pool[b * FLAT + i];
        const float* w = Wd1 + (long)i * 10;
#pragma unroll
        for (int j = 0; j < 10; j++) s[j] = fmaf(v, w[j], s[j]);
    }
    __shared__ float red[10][128];
#pragma unroll
    for (int j = 0; j < 10; j++) red[j][threadIdx.x] = s[j];
    __syncthreads();
    for (int off = 64; off > 0; off >>= 1) {
        if (threadIdx.x < off) {
#pragma unroll
            for (int j = 0; j < 10; j++)
                red[j][threadIdx.x] += red[j][threadIdx.x + off];
        }
        __syncthreads();
    }
    if (threadIdx.x < 10)
        part[(ch * BB + b) * 10 + threadIdx.x] = red[threadIdx.x][0];
}

__global__ void final_kernel(const float* __restrict__ part,
                             const float* __restrict__ bd1,
                             const float* __restrict__ Wd2,
                             const float* __restrict__ bd2,
                             float* __restrict__ out)
{
    __shared__ float sd1[BB][10];
    int tid = threadIdx.x;
    if (tid < BB * 10) {
        int b = tid / 10, j = tid % 10;
        float s = bd1[j];
        for (int ch = 0; ch < NCHUNK; ch++)
            s += part[(ch * BB + b) * 10 + j];
        sd1[b][j] = s;
    }
    __syncthreads();
    if (tid < BB) {
        float o = bd2[0];
#pragma unroll
        for (int j = 0; j < 10; j++)
            o = fmaf(sd1[tid][j], Wd2[j], o);
        out[tid] = o;
    }
}

// ---------------- launcher ----------------
extern "C" void kernel_launch(void* const* d_in, const int* in_sizes, int n_in,
                              void* d_out, int out_size) {
    const float* x   = (const float*)d_in[0];
    const float* W1p = (const float*)d_in[1];
    const float* U1p = (const float*)d_in[2];
    const float* b1p = (const float*)d_in[3];
    const float* W2p = (const float*)d_in[4];
    const float* U2p = (const float*)d_in[5];
    const float* b2p = (const float*)d_in[6];
    const float* Wd1 = (const float*)d_in[7];
    const float* bd1 = (const float*)d_in[8];
    const float* Wd2 = (const float*)d_in[9];
    const float* bd2 = (const float*)d_in[10];
    float* out = (float*)d_out;

    float *h1, *h2, *cb, *hz, *pool, *part;
    float4 *wr1, *ur1, *wr2, *ur2;
    cudaGetSymbolAddress((void**)&h1, g_h1);
    cudaGetSymbolAddress((void**)&h2, g_h2);
    cudaGetSymbolAddress((void**)&cb, g_c);
    cudaGetSymbolAddress((void**)&hz, g_hzero);
    cudaGetSymbolAddress((void**)&pool, g_pool);
    cudaGetSymbolAddress((void**)&part, g_part);
    cudaGetSymbolAddress((void**)&wr1, g_Wr1);
    cudaGetSymbolAddress((void**)&ur1, g_Ur1);
    cudaGetSymbolAddress((void**)&wr2, g_Wr2);
    cudaGetSymbolAddress((void**)&ur2, g_Ur2);

    const int n1 = 6 * C1 * 32, nn = 6 * 32 * 32;
    reorder4_kernel<<<(n1 + 3 * nn + 255) / 256, 256>>>(W1p, wr1, n1,
                                                        U1p, ur1, W2p, wr2, U2p, ur2, nn);
    // zero both layers' cell state in one shot (g_hzero stays zero-init)
    cudaMemsetAsync(cb, 0, sizeof(float) * 2 * BB * HO1 * WO1 * FF, 0);
    float* cb2 = cb + BB * HO1 * WO1 * FF;

    dim3 blk(256);
    dim3 g1((WO1 + 7) / 8, (HO1 + 7) / 8, BB);
    const long h1slice = (long)BB * HO1 * WO1 * FF;
    for (int t = 0; t < TT; t++) {
        const float* xt = x + (long)t * H1 * W1 * C1;
        const float* hp = t ? (h1 + (t - 1) * h1slice) : hz;
        step_kernel<C1><<<g1, blk>>>(xt, TT * H1 * W1 * C1, H1, W1,
                                     hp, cb, h1 + t * h1slice,
                                     wr1, ur1, b1p, HO1, WO1);
    }

    dim3 g2((WO2 + 7) / 8, (HO2 + 7) / 8, BB);
    const long h2slice = (long)BB * HO2 * WO2 * FF;
    for (int t = 0; t < TT; t++) {
        const float* xt = h1 + t * h1slice;
        const float* hp = t ? (h2 + (t - 1) * h2slice) : hz;
        step_kernel<C2><<<g2, blk>>>(xt, HO1 * WO1 * FF, H2, W2,
                                     hp, cb2, h2 + t * h2slice,
                                     wr2, ur2, b2p, HO2, WO2);
    }

    int npool = BB * TT * 23 * 22 * 32;
    pool_kernel<<<(npool + 255) / 256, 256>>>(h2, pool);
    dense_part_kernel<<<dim3(NCHUNK, BB), 128>>>(pool, Wd1, part);
    final_kernel<<<1, 256>>>(part, bd1, Wd2, bd2, out);
}

// round 3
// speedup vs baseline: 1.0935x; 1.0935x over previous
#include <cuda_runtime.h>

typedef unsigned long long u64;

// ---------------- problem constants ----------------
#define BB 16
#define TT 12
#define FF 32
#define H1 48
#define W1 48
#define C1 3
#define HO1 47
#define WO1 46
#define H2 47
#define W2 46
#define C2 32
#define HO2 46
#define WO2 44
#define FLAT 194304
#define NCHUNK 256
#define CHUNK 759   // 256*759 = 194304 exactly

// ---------------- device scratch ----------------
__device__ float g_h1[(long)TT * BB * HO1 * WO1 * FF];
__device__ float g_h2[(long)TT * BB * HO2 * WO2 * FF];
__device__ float g_c[2 * BB * HO1 * WO1 * FF];
__device__ float g_hzero[BB * HO1 * WO1 * FF];          // zero-init, never written
__device__ float g_pool[BB * FLAT];
__device__ float g_part[NCHUNK * BB * 10];
__device__ float4 g_Wr1[6 * C1 * 32];
__device__ float4 g_Ur1[6 * 32 * 32];
__device__ float4 g_Wr2[6 * 32 * 32];
__device__ float4 g_Ur2[6 * 32 * 32];

__device__ __forceinline__ float hsig(float x) {
    return fminf(fmaxf(fmaf(0.2f, x, 0.5f), 0.0f), 1.0f);
}

__device__ __forceinline__ u64 pack2(float lo, float hi) {
    u64 r;
    asm("mov.b64 %0, {%1, %2};" : "=l"(r) : "f"(lo), "f"(hi));
    return r;
}
__device__ __forceinline__ void unpack2(u64 v, float& lo, float& hi) {
    asm("mov.b64 {%0, %1}, %2;" : "=f"(lo), "=f"(hi) : "l"(v));
}
// packed dual fp32 FMA: d = a*b + d
__device__ __forceinline__ void ffma2(u64& d, u64 a, u64 b) {
    asm("fma.rn.f32x2 %0, %1, %2, %0;" : "+l"(d) : "l"(a), "l"(b));
}

// Combined weight reorder: [k(6)][cin][128] -> float4 {i,f,c,o} per (k,cin,f)
__global__ void reorder4_kernel(const float* __restrict__ s1, float4* __restrict__ d1, int n1,
                                const float* __restrict__ s2, float4* __restrict__ d2,
                                const float* __restrict__ s3, float4* __restrict__ d3,
                                const float* __restrict__ s4, float4* __restrict__ d4, int n) {
    int idx = blockIdx.x * blockDim.x + threadIdx.x;
    if (idx < n1) {
        int f = idx & 31, kc = idx >> 5;
        const float* s = s1 + kc * 128;
        d1[idx] = make_float4(s[f], s[32 + f], s[64 + f], s[96 + f]);
    } else if (idx < n1 + 3 * n) {
        int j = idx - n1;
        int seg = j / n;
        int e = j % n;
        int f = e & 31, kc = e >> 5;
        const float* s = (seg == 0 ? s2 : seg == 1 ? s3 : s4) + kc * 128;
        float4* d = (seg == 0 ? d2 : seg == 1 ? d3 : d4) + e;
        *d = make_float4(s[f], s[32 + f], s[64 + f], s[96 + f]);
    }
}

// One conv segment: accumulate 6-tap conv over CIN channels for a 2x4 thread tile.
// buf layout: [(row*10 + col)*CIN + ci] of {v,v} u64 pairs.
// ry = input row base (2*wy), cx = col base (4*wx).
template <int CIN>
__device__ __forceinline__ void conv_seg(const u64* __restrict__ buf,
                                         const float4* __restrict__ Wt,
                                         int f, int ry, int cx,
                                         u64 aif[2][4], u64 aco[2][4])
{
#pragma unroll 2
    for (int ci = 0; ci < CIN; ci++) {
        u64 wif[6], wco[6];
#pragma unroll
        for (int k = 0; k < 6; k++) {
            float4 w = Wt[(k * CIN + ci) * 32 + f];
            wif[k] = pack2(w.x, w.y);
            wco[k] = pack2(w.z, w.w);
        }
#pragma unroll
        for (int ir = 0; ir < 3; ir++) {
            u64 v[6];
#pragma unroll
            for (int j = 0; j < 6; j++)
                v[j] = buf[((ry + ir) * 10 + cx + j) * CIN + ci];
#pragma unroll
            for (int dx = 0; dx < 3; dx++) {
#pragma unroll
                for (int p = 0; p < 4; p++) {
                    if (ir < 2) {                      // dy = 0 for out row ir
                        ffma2(aif[ir][p], v[p + dx], wif[dx]);
                        ffma2(aco[ir][p], v[p + dx], wco[dx]);
                    }
                    if (ir >= 1) {                     // dy = 1 for out row ir-1
                        ffma2(aif[ir - 1][p], v[p + dx], wif[3 + dx]);
                        ffma2(aco[ir - 1][p], v[p + dx], wco[3 + dx]);
                    }
                }
            }
        }
    }
}

// Fused ConvLSTM timestep. Block 256 = 8 warps; warp -> (wy, wx) sub-tile of the
// 8x8 block tile; lane = filter. Thread computes 2 rows x 4 cols x 4 gates.
template <int CIN>
__global__ void __launch_bounds__(256, 2) step_kernel(
    const float* __restrict__ xin, int xbstride, int H, int W,
    const float* __restrict__ hprev,
    float* __restrict__ cbuf,
    float* __restrict__ hout,
    const float4* __restrict__ Wr, const float4* __restrict__ Ur,
    const float* __restrict__ bias,
    int Ho, int Wo)
{
    __shared__ u64 xs[9 * 10 * CIN];
    __shared__ u64 hs[9 * 10 * 32];

    const int tid = threadIdx.x;
    const int f = tid & 31;
    const int wp = tid >> 5;
    const int wy = wp >> 1;          // 0..3
    const int wx = wp & 1;           // 0..1
    const int b = blockIdx.z;
    const int y0 = blockIdx.y * 8;
    const int x0 = blockIdx.x * 8;
    const int hb = Ho * Wo * 32;

    // stage x patch (duplicated {v,v})
    for (int i = tid; i < 9 * 10 * CIN; i += 256) {
        int ci = i % CIN; int t2 = i / CIN;
        int cx = t2 % 10; int r = t2 / 10;
        int gy = y0 + r, gx = x0 + cx;
        float v = 0.0f;
        if (gy < H && gx < W)
            v = xin[(long)b * xbstride + (gy * W + gx) * CIN + ci];
        xs[(r * 10 + cx) * CIN + ci] = pack2(v, v);
    }
    // stage h patch (SAME pad: top 0/bottom 1, left 1/right 1); col 0 == x0-1
    for (int i = tid; i < 9 * 10 * 32; i += 256) {
        int ci = i & 31; int t2 = i >> 5;
        int cx = t2 % 10; int r = t2 / 10;
        int gy = y0 + r, gx = x0 + cx - 1;
        float v = 0.0f;
        if (gy < Ho && gx >= 0 && gx < Wo)
            v = hprev[(long)b * hb + (gy * Wo + gx) * 32 + ci];
        hs[(r * 10 + cx) * 32 + ci] = pack2(v, v);
    }
    __syncthreads();

    u64 aif[2][4], aco[2][4];
    {
        u64 bif = pack2(bias[f], bias[32 + f]);
        u64 bco = pack2(bias[64 + f], bias[96 + f]);
#pragma unroll
        for (int r = 0; r < 2; r++)
#pragma unroll
            for (int p = 0; p < 4; p++) { aif[r][p] = bif; aco[r][p] = bco; }
    }

    const int ry = 2 * wy;
    const int cx4 = 4 * wx;
    conv_seg<CIN>(xs, Wr, f, ry, cx4, aif, aco);   // input conv (VALID)
    conv_seg<32>(hs, Ur, f, ry, cx4, aif, aco);    // recurrent conv (SAME)

    // gates + state update
#pragma unroll
    for (int r = 0; r < 2; r++) {
        int y = y0 + ry + r;
        if (y < Ho) {
#pragma unroll
            for (int p = 0; p < 4; p++) {
                int gx = x0 + cx4 + p;
                if (gx < Wo) {
                    long o = (long)b * hb + (y * Wo + gx) * 32 + f;
                    float zi, zf, zc, zo;
                    unpack2(aif[r][p], zi, zf);
                    unpack2(aco[r][p], zc, zo);
                    float cold = cbuf[o];
                    float ig = hsig(zi);
                    float fg = hsig(zf);
                    float cn = fmaf(fg, cold, ig * fmaxf(zc, 0.0f));
                    cbuf[o] = cn;
                    hout[o] = hsig(zo) * fmaxf(cn, 0.0f);
                }
            }
        }
    }
}

// MaxPool (1,2,2): h2 [T][B][46][44][32] -> pool [B][T][23][22][32]
__global__ void pool_kernel(const float* __restrict__ h2, float* __restrict__ pout) {
    int idx = blockIdx.x * blockDim.x + threadIdx.x;
    if (idx >= BB * TT * 23 * 22 * 32) return;
    int c = idx & 31; int t2 = idx >> 5;
    int pw = t2 % 22; t2 /= 22;
    int ph = t2 % 23; t2 /= 23;
    int t = t2 % TT; int b = t2 / TT;
    const float* base = h2 + (((long)(t * BB + b) * HO2 + 2 * ph) * WO2 + 2 * pw) * 32 + c;
    float m = fmaxf(fmaxf(base[0], base[32]),
                    fmaxf(base[WO2 * 32], base[WO2 * 32 + 32]));
    pout[idx] = m;
}

__global__ void __launch_bounds__(128) dense_part_kernel(
    const float* __restrict__ pool, const float* __restrict__ Wd1, float* __restrict__ part)
{
    int ch = blockIdx.x, b = blockIdx.y;
    int start = ch * CHUNK;
    float s[10];
#pragma unroll
    for (int j = 0; j < 10; j++) s[j] = 0.0f;
    for (int i = start + threadIdx.x; i < start + CHUNK; i += 128) {
        float v = pool[b * FLAT + i];
        const float* w = Wd1 + (long)i * 10;
#pragma unroll
        for (int j = 0; j < 10; j++) s[j] = fmaf(v, w[j], s[j]);
    }
    __shared__ float red[10][128];
#pragma unroll
    for (int j = 0; j < 10; j++) red[j][threadIdx.x] = s[j];
    __syncthreads();
    for (int off = 64; off > 0; off >>= 1) {
        if (threadIdx.x < off) {
#pragma unroll
            for (int j = 0; j < 10; j++)
                red[j][threadIdx.x] += red[j][threadIdx.x + off];
        }
        __syncthreads();
    }
    if (threadIdx.x < 10)
        part[(ch * BB + b) * 10 + threadIdx.x] = red[threadIdx.x][0];
}

__global__ void final_kernel(const float* __restrict__ part,
                             const float* __restrict__ bd1,
                             const float* __restrict__ Wd2,
                             const float* __restrict__ bd2,
                             float* __restrict__ out)
{
    __shared__ float sd1[BB][10];
    int tid = threadIdx.x;
    if (tid < BB * 10) {
        int b = tid / 10, j = tid % 10;
        float s = bd1[j];
        for (int ch = 0; ch < NCHUNK; ch++)
            s += part[(ch * BB + b) * 10 + j];
        sd1[b][j] = s;
    }
    __syncthreads();
    if (tid < BB) {
        float o = bd2[0];
#pragma unroll
        for (int j = 0; j < 10; j++)
            o = fmaf(sd1[tid][j], Wd2[j], o);
        out[tid] = o;
    }
}

// ---------------- launcher ----------------
extern "C" void kernel_launch(void* const* d_in, const int* in_sizes, int n_in,
                              void* d_out, int out_size) {
    const float* x   = (const float*)d_in[0];
    const float* W1p = (const float*)d_in[1];
    const float* U1p = (const float*)d_in[2];
    const float* b1p = (const float*)d_in[3];
    const float* W2p = (const float*)d_in[4];
    const float* U2p = (const float*)d_in[5];
    const float* b2p = (const float*)d_in[6];
    const float* Wd1 = (const float*)d_in[7];
    const float* bd1 = (const float*)d_in[8];
    const float* Wd2 = (const float*)d_in[9];
    const float* bd2 = (const float*)d_in[10];
    float* out = (float*)d_out;

    float *h1, *h2, *cb, *hz, *pool, *part;
    float4 *wr1, *ur1, *wr2, *ur2;
    cudaGetSymbolAddress((void**)&h1, g_h1);
    cudaGetSymbolAddress((void**)&h2, g_h2);
    cudaGetSymbolAddress((void**)&cb, g_c);
    cudaGetSymbolAddress((void**)&hz, g_hzero);
    cudaGetSymbolAddress((void**)&pool, g_pool);
    cudaGetSymbolAddress((void**)&part, g_part);
    cudaGetSymbolAddress((void**)&wr1, g_Wr1);
    cudaGetSymbolAddress((void**)&ur1, g_Ur1);
    cudaGetSymbolAddress((void**)&wr2, g_Wr2);
    cudaGetSymbolAddress((void**)&ur2, g_Ur2);

    const int n1 = 6 * C1 * 32, nn = 6 * 32 * 32;
    reorder4_kernel<<<(n1 + 3 * nn + 255) / 256, 256>>>(W1p, wr1, n1,
                                                        U1p, ur1, W2p, wr2, U2p, ur2, nn);
    cudaMemsetAsync(cb, 0, sizeof(float) * 2 * BB * HO1 * WO1 * FF, 0);
    float* cb2 = cb + BB * HO1 * WO1 * FF;

    dim3 blk(256);
    dim3 g1((WO1 + 7) / 8, (HO1 + 7) / 8, BB);
    const long h1slice = (long)BB * HO1 * WO1 * FF;
    for (int t = 0; t < TT; t++) {
        const float* xt = x + (long)t * H1 * W1 * C1;
        const float* hp = t ? (h1 + (t - 1) * h1slice) : hz;
        step_kernel<C1><<<g1, blk>>>(xt, TT * H1 * W1 * C1, H1, W1,
                                     hp, cb, h1 + t * h1slice,
                                     wr1, ur1, b1p, HO1, WO1);
    }

    dim3 g2((WO2 + 7) / 8, (HO2 + 7) / 8, BB);
    const long h2slice = (long)BB * HO2 * WO2 * FF;
    for (int t = 0; t < TT; t++) {
        const float* xt = h1 + t * h1slice;
        const float* hp = t ? (h2 + (t - 1) * h2slice) : hz;
        step_kernel<C2><<<g2, blk>>>(xt, HO1 * WO1 * FF, H2, W2,
                                     hp, cb2, h2 + t * h2slice,
                                     wr2, ur2, b2p, HO2, WO2);
    }

    int npool = BB * TT * 23 * 22 * 32;
    pool_kernel<<<(npool + 255) / 256, 256>>>(h2, pool);
    dense_part_kernel<<<dim3(NCHUNK, BB), 128>>>(pool, Wd1, part);
    final_kernel<<<1, 256>>>(part, bd1, Wd2, bd2, out);
}

// round 4
// speedup vs baseline: 1.0957x; 1.0020x over previous
#include <cuda_runtime.h>

typedef unsigned long long u64;

// ---------------- problem constants ----------------
#define BB 16
#define TT 12
#define FF 32
#define H1 48
#define W1 48
#define C1 3
#define HO1 47
#define WO1 46
#define H2 47
#define W2 46
#define C2 32
#define HO2 46
#define WO2 44
#define FLAT 194304
#define NCHUNK 256
#define CHUNK 759   // 256*759 = 194304 exactly

// ---------------- device scratch ----------------
__device__ float g_h1[(long)TT * BB * HO1 * WO1 * FF];
__device__ float g_h2[(long)TT * BB * HO2 * WO2 * FF];
__device__ float g_c[2 * BB * HO1 * WO1 * FF];
__device__ float g_hzero[BB * HO1 * WO1 * FF];          // zero-init, never written
__device__ float g_pool[BB * FLAT];
__device__ float g_part[NCHUNK * BB * 10];
__device__ float4 g_Wr1[6 * C1 * 32];
__device__ float4 g_Ur1[6 * 32 * 32];
__device__ float4 g_Wr2[6 * 32 * 32];
__device__ float4 g_Ur2[6 * 32 * 32];

__device__ __forceinline__ float hsig(float x) {
    return fminf(fmaxf(fmaf(0.2f, x, 0.5f), 0.0f), 1.0f);
}

__device__ __forceinline__ u64 pack2(float lo, float hi) {
    u64 r;
    asm("mov.b64 %0, {%1, %2};" : "=l"(r) : "f"(lo), "f"(hi));
    return r;
}
__device__ __forceinline__ void unpack2(u64 v, float& lo, float& hi) {
    asm("mov.b64 {%0, %1}, %2;" : "=f"(lo), "=f"(hi) : "l"(v));
}
// packed dual fp32 FMA: d = a*b + d
__device__ __forceinline__ void ffma2(u64& d, u64 a, u64 b) {
    asm("fma.rn.f32x2 %0, %1, %2, %0;" : "+l"(d) : "l"(a), "l"(b));
}

// Combined weight reorder: [k(6)][cin][128] -> float4 {i,f,c,o} per (k,cin,f)
__global__ void reorder4_kernel(const float* __restrict__ s1, float4* __restrict__ d1, int n1,
                                const float* __restrict__ s2, float4* __restrict__ d2,
                                const float* __restrict__ s3, float4* __restrict__ d3,
                                const float* __restrict__ s4, float4* __restrict__ d4, int n) {
    int idx = blockIdx.x * blockDim.x + threadIdx.x;
    if (idx < n1) {
        int f = idx & 31, kc = idx >> 5;
        const float* s = s1 + kc * 128;
        d1[idx] = make_float4(s[f], s[32 + f], s[64 + f], s[96 + f]);
    } else if (idx < n1 + 3 * n) {
        int j = idx - n1;
        int seg = j / n;
        int e = j % n;
        int f = e & 31, kc = e >> 5;
        const float* s = (seg == 0 ? s2 : seg == 1 ? s3 : s4) + kc * 128;
        float4* d = (seg == 0 ? d2 : seg == 1 ? d3 : d4) + e;
        *d = make_float4(s[f], s[32 + f], s[64 + f], s[96 + f]);
    }
}

// One conv segment: accumulate 6-tap conv over CIN channels for a 2x4 thread tile.
// buf layout: [(row*10 + col)*CIN + ci] of {v,v} u64 pairs.
// ry = input row base (2*wy), cx = col base (4*wx).
template <int CIN>
__device__ __forceinline__ void conv_seg(const u64* __restrict__ buf,
                                         const float4* __restrict__ Wt,
                                         int f, int ry, int cx,
                                         u64 aif[2][4], u64 aco[2][4])
{
#pragma unroll 2
    for (int ci = 0; ci < CIN; ci++) {
        u64 wif[6], wco[6];
#pragma unroll
        for (int k = 0; k < 6; k++) {
            float4 w = Wt[(k * CIN + ci) * 32 + f];
            wif[k] = pack2(w.x, w.y);
            wco[k] = pack2(w.z, w.w);
        }
#pragma unroll
        for (int ir = 0; ir < 3; ir++) {
            u64 v[6];
#pragma unroll
            for (int j = 0; j < 6; j++)
                v[j] = buf[((ry + ir) * 10 + cx + j) * CIN + ci];
#pragma unroll
            for (int dx = 0; dx < 3; dx++) {
#pragma unroll
                for (int p = 0; p < 4; p++) {
                    if (ir < 2) {                      // dy = 0 for out row ir
                        ffma2(aif[ir][p], v[p + dx], wif[dx]);
                        ffma2(aco[ir][p], v[p + dx], wco[dx]);
                    }
                    if (ir >= 1) {                     // dy = 1 for out row ir-1
                        ffma2(aif[ir - 1][p], v[p + dx], wif[3 + dx]);
                        ffma2(aco[ir - 1][p], v[p + dx], wco[3 + dx]);
                    }
                }
            }
        }
    }
}

// Fused ConvLSTM timestep. Block 256 = 8 warps; warp -> (wy, wx) sub-tile of the
// 8x8 block tile; lane = filter. Thread computes 2 rows x 4 cols x 4 gates.
template <int CIN>
__global__ void __launch_bounds__(256, 2) step_kernel(
    const float* __restrict__ xin, int xbstride, int H, int W,
    const float* __restrict__ hprev,
    float* __restrict__ cbuf,
    float* __restrict__ hout,
    const float4* __restrict__ Wr, const float4* __restrict__ Ur,
    const float* __restrict__ bias,
    int Ho, int Wo)
{
    __shared__ u64 xs[9 * 10 * CIN];
    __shared__ u64 hs[9 * 10 * 32];

    const int tid = threadIdx.x;
    const int f = tid & 31;
    const int wp = tid >> 5;
    const int wy = wp >> 1;          // 0..3
    const int wx = wp & 1;           // 0..1
    const int b = blockIdx.z;
    const int y0 = blockIdx.y * 8;
    const int x0 = blockIdx.x * 8;
    const int hb = Ho * Wo * 32;

    // stage x patch (duplicated {v,v})
    for (int i = tid; i < 9 * 10 * CIN; i += 256) {
        int ci = i % CIN; int t2 = i / CIN;
        int cx = t2 % 10; int r = t2 / 10;
        int gy = y0 + r, gx = x0 + cx;
        float v = 0.0f;
        if (gy < H && gx < W)
            v = xin[(long)b * xbstride + (gy * W + gx) * CIN + ci];
        xs[(r * 10 + cx) * CIN + ci] = pack2(v, v);
    }
    // stage h patch (SAME pad: top 0/bottom 1, left 1/right 1); col 0 == x0-1
    for (int i = tid; i < 9 * 10 * 32; i += 256) {
        int ci = i & 31; int t2 = i >> 5;
        int cx = t2 % 10; int r = t2 / 10;
        int gy = y0 + r, gx = x0 + cx - 1;
        float v = 0.0f;
        if (gy < Ho && gx >= 0 && gx < Wo)
            v = hprev[(long)b * hb + (gy * Wo + gx) * 32 + ci];
        hs[(r * 10 + cx) * 32 + ci] = pack2(v, v);
    }
    __syncthreads();

    u64 aif[2][4], aco[2][4];
    {
        u64 bif = pack2(bias[f], bias[32 + f]);
        u64 bco = pack2(bias[64 + f], bias[96 + f]);
#pragma unroll
        for (int r = 0; r < 2; r++)
#pragma unroll
            for (int p = 0; p < 4; p++) { aif[r][p] = bif; aco[r][p] = bco; }
    }

    const int ry = 2 * wy;
    const int cx4 = 4 * wx;
    conv_seg<CIN>(xs, Wr, f, ry, cx4, aif, aco);   // input conv (VALID)
    conv_seg<32>(hs, Ur, f, ry, cx4, aif, aco);    // recurrent conv (SAME)

    // gates + state update
#pragma unroll
    for (int r = 0; r < 2; r++) {
        int y = y0 + ry + r;
        if (y < Ho) {
#pragma unroll
            for (int p = 0; p < 4; p++) {
                int gx = x0 + cx4 + p;
                if (gx < Wo) {
                    long o = (long)b * hb + (y * Wo + gx) * 32 + f;
                    float zi, zf, zc, zo;
                    unpack2(aif[r][p], zi, zf);
                    unpack2(aco[r][p], zc, zo);
                    float cold = cbuf[o];
                    float ig = hsig(zi);
                    float fg = hsig(zf);
                    float cn = fmaf(fg, cold, ig * fmaxf(zc, 0.0f));
                    cbuf[o] = cn;
                    hout[o] = hsig(zo) * fmaxf(cn, 0.0f);
                }
            }
        }
    }
}

// MaxPool (1,2,2): h2 [T][B][46][44][32] -> pool [B][T][23][22][32]
__global__ void pool_kernel(const float* __restrict__ h2, float* __restrict__ pout) {
    int idx = blockIdx.x * blockDim.x + threadIdx.x;
    if (idx >= BB * TT * 23 * 22 * 32) return;
    int c = idx & 31; int t2 = idx >> 5;
    int pw = t2 % 22; t2 /= 22;
    int ph = t2 % 23; t2 /= 23;
    int t = t2 % TT; int b = t2 / TT;
    const float* base = h2 + (((long)(t * BB + b) * HO2 + 2 * ph) * WO2 + 2 * pw) * 32 + c;
    float m = fmaxf(fmaxf(base[0], base[32]),
                    fmaxf(base[WO2 * 32], base[WO2 * 32 + 32]));
    pout[idx] = m;
}

__global__ void __launch_bounds__(128) dense_part_kernel(
    const float* __restrict__ pool, const float* __restrict__ Wd1, float* __restrict__ part)
{
    int ch = blockIdx.x, b = blockIdx.y;
    int start = ch * CHUNK;
    float s[10];
#pragma unroll
    for (int j = 0; j < 10; j++) s[j] = 0.0f;
    for (int i = start + threadIdx.x; i < start + CHUNK; i += 128) {
        float v = pool[b * FLAT + i];
        const float* w = Wd1 + (long)i * 10;
#pragma unroll
        for (int j = 0; j < 10; j++) s[j] = fmaf(v, w[j], s[j]);
    }
    __shared__ float red[10][128];
#pragma unroll
    for (int j = 0; j < 10; j++) red[j][threadIdx.x] = s[j];
    __syncthreads();
    for (int off = 64; off > 0; off >>= 1) {
        if (threadIdx.x < off) {
#pragma unroll
            for (int j = 0; j < 10; j++)
                red[j][threadIdx.x] += red[j][threadIdx.x + off];
        }
        __syncthreads();
    }
    if (threadIdx.x < 10)
        part[(ch * BB + b) * 10 + threadIdx.x] = red[threadIdx.x][0];
}

__global__ void final_kernel(const float* __restrict__ part,
                             const float* __restrict__ bd1,
                             const float* __restrict__ Wd2,
                             const float* __restrict__ bd2,
                             float* __restrict__ out)
{
    __shared__ float sd1[BB][10];
    int tid = threadIdx.x;
    if (tid < BB * 10) {
        int b = tid / 10, j = tid % 10;
        float s = bd1[j];
        for (int ch = 0; ch < NCHUNK; ch++)
            s += part[(ch * BB + b) * 10 + j];
        sd1[b][j] = s;
    }
    __syncthreads();
    if (tid < BB) {
        float o = bd2[0];
#pragma unroll
        for (int j = 0; j < 10; j++)
            o = fmaf(sd1[tid][j], Wd2[j], o);
        out[tid] = o;
    }
}

// ---------------- launcher ----------------
extern "C" void kernel_launch(void* const* d_in, const int* in_sizes, int n_in,
                              void* d_out, int out_size) {
    const float* x   = (const float*)d_in[0];
    const float* W1p = (const float*)d_in[1];
    const float* U1p = (const float*)d_in[2];
    const float* b1p = (const float*)d_in[3];
    const float* W2p = (const float*)d_in[4];
    const float* U2p = (const float*)d_in[5];
    const float* b2p = (const float*)d_in[6];
    const float* Wd1 = (const float*)d_in[7];
    const float* bd1 = (const float*)d_in[8];
    const float* Wd2 = (const float*)d_in[9];
    const float* bd2 = (const float*)d_in[10];
    float* out = (float*)d_out;

    float *h1, *h2, *cb, *hz, *pool, *part;
    float4 *wr1, *ur1, *wr2, *ur2;
    cudaGetSymbolAddress((void**)&h1, g_h1);
    cudaGetSymbolAddress((void**)&h2, g_h2);
    cudaGetSymbolAddress((void**)&cb, g_c);
    cudaGetSymbolAddress((void**)&hz, g_hzero);
    cudaGetSymbolAddress((void**)&pool, g_pool);
    cudaGetSymbolAddress((void**)&part, g_part);
    cudaGetSymbolAddress((void**)&wr1, g_Wr1);
    cudaGetSymbolAddress((void**)&ur1, g_Ur1);
    cudaGetSymbolAddress((void**)&wr2, g_Wr2);
    cudaGetSymbolAddress((void**)&ur2, g_Ur2);

    const int n1 = 6 * C1 * 32, nn = 6 * 32 * 32;
    reorder4_kernel<<<(n1 + 3 * nn + 255) / 256, 256>>>(W1p, wr1, n1,
                                                        U1p, ur1, W2p, wr2, U2p, ur2, nn);
    cudaMemsetAsync(cb, 0, sizeof(float) * 2 * BB * HO1 * WO1 * FF, 0);
    float* cb2 = cb + BB * HO1 * WO1 * FF;

    dim3 blk(256);
    dim3 g1((WO1 + 7) / 8, (HO1 + 7) / 8, BB);
    const long h1slice = (long)BB * HO1 * WO1 * FF;
    for (int t = 0; t < TT; t++) {
        const float* xt = x + (long)t * H1 * W1 * C1;
        const float* hp = t ? (h1 + (t - 1) * h1slice) : hz;
        step_kernel<C1><<<g1, blk>>>(xt, TT * H1 * W1 * C1, H1, W1,
                                     hp, cb, h1 + t * h1slice,
                                     wr1, ur1, b1p, HO1, WO1);
    }

    dim3 g2((WO2 + 7) / 8, (HO2 + 7) / 8, BB);
    const long h2slice = (long)BB * HO2 * WO2 * FF;
    for (int t = 0; t < TT; t++) {
        const float* xt = h1 + t * h1slice;
        const float* hp = t ? (h2 + (t - 1) * h2slice) : hz;
        step_kernel<C2><<<g2, blk>>>(xt, HO1 * WO1 * FF, H2, W2,
                                     hp, cb2, h2 + t * h2slice,
                                     wr2, ur2, b2p, HO2, WO2);
    }

    int npool = BB * TT * 23 * 22 * 32;
    pool_kernel<<<(npool + 255) / 256, 256>>>(h2, pool);
    dense_part_kernel<<<dim3(NCHUNK, BB), 128>>>(pool, Wd1, part);
    final_kernel<<<1, 256>>>(part, bd1, Wd2, bd2, out);
}